// round 10
// baseline (speedup 1.0000x reference)
#include <cuda_runtime.h>

// Problem constants
#define NN   4096
#define DD   2048
#define CC   128
#define D4   (DD/4)          // 512 float4 per row
#define MTOT 256             // stacked rows: 0..127 = CR, 128..255 = CT
#define MT   32              // gram m-tile per block
#define KS   32              // k slices
#define KSL  64              // k per slice (KS*KSL == DD)

// ---------------- device scratch (no allocation allowed) ----------------
__device__ int   g_cnt[CC];
__device__ float g_C  [MTOT * DD];       // class means [m][k]: CR rows then CT rows
__device__ float g_nPart[2][3][CC];      // per-col-half norm partials (R,T,M)
__device__ float g_P2[KS][MTOT * CC];    // Gram K-partials, fixed slots (4 MB)
__device__ float g_la2[2 * CC];          // per (half, class-row) loss partials
__device__ int   g_ctr = 0;              // last-block counter (self-resetting)

// ---------------- f32x2 helpers (FFMA2 path) ----------------
__device__ __forceinline__ unsigned long long pack2(float x, float y) {
    unsigned long long r;
    asm("mov.b64 %0, {%1, %2};" : "=l"(r) : "f"(x), "f"(y));
    return r;
}
__device__ __forceinline__ unsigned long long fma2(unsigned long long a,
                                                   unsigned long long b,
                                                   unsigned long long c) {
    unsigned long long d;
    asm("fma.rn.f32x2 %0, %1, %2, %3;" : "=l"(d) : "l"(a), "l"(b), "l"(c));
    return d;
}
__device__ __forceinline__ float2 unpack2(unsigned long long v) {
    float2 f;
    asm("mov.b64 {%0, %1}, %2;" : "=f"(f.x), "=f"(f.y) : "l"(v));
    return f;
}

// ---------------- K1: fused warp-scan classlist + per-class means + norms -----
// grid (CC, 2), 256 threads. Warp-local scans (no block syncs in the scan loop),
// deterministic concat, then the column-half gather. Carries the 64MB read.
__global__ void __launch_bounds__(256) k_means(const float* __restrict__ m1,
                                               const float* __restrict__ m2,
                                               const int*   __restrict__ targets) {
    int c = blockIdx.x, y = blockIdx.y, tid = threadIdx.x;
    int lane = tid & 31, warp = tid >> 5;

    __shared__ int s_list[8][512];    // per-warp candidate lists (worst-case safe)
    __shared__ int s_cnt[8];
    __shared__ int s_idx[NN];

    // warp w scans targets[w*512 .. +512) independently — no block barriers
    {
        int base = warp * 512;
        int cntw = 0;
        unsigned lt = (1u << lane) - 1u;
        #pragma unroll 4
        for (int j = 0; j < 16; j++) {
            int i = base + j * 32 + lane;
            int t = targets[i];
            bool flag = (t == c);
            unsigned mask = __ballot_sync(0xffffffffu, flag);
            if (flag) s_list[warp][cntw + __popc(mask & lt)] = i;
            cntw += __popc(mask);
        }
        if (lane == 0) s_cnt[warp] = cntw;
    }
    __syncthreads();

    int cnt = 0, off = 0;
    #pragma unroll
    for (int w = 0; w < 8; w++) {
        int v = s_cnt[w];
        if (w < warp) off += v;
        cnt += v;
    }
    if (cnt > NN) cnt = NN;
    {   // deterministic concat: warp w copies its list to its fixed offset
        int n = s_cnt[warp];
        for (int i = lane; i < n; i += 32) s_idx[off + i] = s_list[warp][i];
    }
    __syncthreads();

    // gather: this block owns 256 consecutive float4 columns
    int col4 = y * 256 + tid;     // 0..511
    const float4* __restrict__ m1v = (const float4*)m1;
    const float4* __restrict__ m2v = (const float4*)m2;

    float4 sR = make_float4(0.f, 0.f, 0.f, 0.f);
    float4 sT = make_float4(0.f, 0.f, 0.f, 0.f);
    int k = 0;
    for (; k + 8 <= cnt; k += 8) {
        #pragma unroll
        for (int u = 0; u < 8; u++) {
            int r = s_idx[k + u];
            float4 a = m1v[r * D4 + col4];
            float4 b = m2v[r * D4 + col4];
            sR.x += a.x; sR.y += a.y; sR.z += a.z; sR.w += a.w;
            sT.x += b.x; sT.y += b.y; sT.z += b.z; sT.w += b.w;
        }
    }
    for (; k < cnt; k++) {
        int r = s_idx[k];
        float4 a = m1v[r * D4 + col4];
        float4 b = m2v[r * D4 + col4];
        sR.x += a.x; sR.y += a.y; sR.z += a.z; sR.w += a.w;
        sT.x += b.x; sT.y += b.y; sT.z += b.z; sT.w += b.w;
    }

    float inv = 1.0f / (float)(cnt > 0 ? cnt : 1);
    float4 mr = make_float4(sR.x * inv, sR.y * inv, sR.z * inv, sR.w * inv);
    float4 mt = make_float4(sT.x * inv, sT.y * inv, sT.z * inv, sT.w * inv);
    float4 mm = make_float4(0.5f * (mr.x + mt.x), 0.5f * (mr.y + mt.y),
                            0.5f * (mr.z + mt.z), 0.5f * (mr.w + mt.w));

    ((float4*)g_C)[c * D4 + col4]        = mr;
    ((float4*)g_C)[(CC + c) * D4 + col4] = mt;

    // norm partials over this column half (fixed-tree reduce)
    float pR = mr.x * mr.x + mr.y * mr.y + mr.z * mr.z + mr.w * mr.w;
    float pT = mt.x * mt.x + mt.y * mt.y + mt.z * mt.z + mt.w * mt.w;
    float pM = mm.x * mm.x + mm.y * mm.y + mm.z * mm.z + mm.w * mm.w;
    __shared__ float r0[256], r1[256], r2[256];
    r0[tid] = pR; r1[tid] = pT; r2[tid] = pM;
    __syncthreads();
    for (int s = 128; s > 0; s >>= 1) {
        if (tid < s) { r0[tid] += r0[tid + s]; r1[tid] += r1[tid + s]; r2[tid] += r2[tid + s]; }
        __syncthreads();
    }
    if (tid == 0) {
        g_nPart[y][0][c] = r0[0];
        g_nPart[y][1][c] = r1[0];
        g_nPart[y][2][c] = r2[0];
        if (y == 0) g_cnt[c] = cnt;
    }
}

// ---------------- K2: Gram with inline transpose + B build --------------------
// grid (MTOT/MT = 8, KS = 32) = 256 blocks, 256 threads.
// Loads A rows + builds Cm = 0.5(CR+CT) in smem directly from row-major g_C
// (coalesced float4 LDG, ~2-way STS fill). Main loop: conflict-free scalar
// LDS (pad 67: delta 67 == 3 mod 32) + broadcast A + FFMA2 into 4x4 tile.
__global__ void __launch_bounds__(256) k_gram() {
    __shared__ float Acm[MT][67];       // [row][k], 8.6 KB
    __shared__ float Bcm[CC][67];       // [c][k] = Cm, 34.3 KB

    int tid = threadIdx.x;
    int m0  = blockIdx.x * MT;
    int kb4 = blockIdx.y * (KSL / 4);

    const float4* __restrict__ c4 = (const float4*)g_C;

    // A fill: 32 rows x 16 float4 = 512 float4 (2 per thread), coalesced LDG
    #pragma unroll
    for (int i = 0; i < 2; i++) {
        int idx = tid + i * 256;           // 0..511
        int r = idx >> 4, j4 = idx & 15;
        float4 v = c4[(m0 + r) * D4 + kb4 + j4];
        Acm[r][j4 * 4 + 0] = v.x;
        Acm[r][j4 * 4 + 1] = v.y;
        Acm[r][j4 * 4 + 2] = v.z;
        Acm[r][j4 * 4 + 3] = v.w;
    }
    // B fill: 128 classes x 16 float4, CR + CT pair per float4 (8 per thread)
    #pragma unroll
    for (int i = 0; i < 8; i++) {
        int idx = tid + i * 256;           // 0..2047
        int cc = idx >> 4, j4 = idx & 15;
        float4 vR = c4[cc * D4 + kb4 + j4];
        float4 vT = c4[(CC + cc) * D4 + kb4 + j4];
        Bcm[cc][j4 * 4 + 0] = 0.5f * (vR.x + vT.x);
        Bcm[cc][j4 * 4 + 1] = 0.5f * (vR.y + vT.y);
        Bcm[cc][j4 * 4 + 2] = 0.5f * (vR.z + vT.z);
        Bcm[cc][j4 * 4 + 3] = 0.5f * (vR.w + vT.w);
    }
    __syncthreads();

    int tx = tid & 31;     // cols tx, tx+32, tx+64, tx+96
    int ty = tid >> 5;     // rows ty*4 .. ty*4+3 (warp-uniform -> LDS broadcast)

    // acc2[q][p]: col q, p=0 rows (0,1), p=1 rows (2,3)
    unsigned long long acc2[4][2];
    #pragma unroll
    for (int q = 0; q < 4; q++) { acc2[q][0] = 0ull; acc2[q][1] = 0ull; }

    #pragma unroll 8
    for (int k = 0; k < KSL; k++) {
        float a0 = Acm[ty * 4 + 0][k];
        float a1 = Acm[ty * 4 + 1][k];
        float a2 = Acm[ty * 4 + 2][k];
        float a3 = Acm[ty * 4 + 3][k];
        float b0 = Bcm[tx      ][k];
        float b1 = Bcm[tx + 32 ][k];
        float b2 = Bcm[tx + 64 ][k];
        float b3 = Bcm[tx + 96 ][k];
        unsigned long long a01 = pack2(a0, a1);
        unsigned long long a23 = pack2(a2, a3);
        unsigned long long B0 = pack2(b0, b0);
        unsigned long long B1 = pack2(b1, b1);
        unsigned long long B2 = pack2(b2, b2);
        unsigned long long B3 = pack2(b3, b3);
        acc2[0][0] = fma2(a01, B0, acc2[0][0]);
        acc2[0][1] = fma2(a23, B0, acc2[0][1]);
        acc2[1][0] = fma2(a01, B1, acc2[1][0]);
        acc2[1][1] = fma2(a23, B1, acc2[1][1]);
        acc2[2][0] = fma2(a01, B2, acc2[2][0]);
        acc2[2][1] = fma2(a23, B2, acc2[2][1]);
        acc2[3][0] = fma2(a01, B3, acc2[3][0]);
        acc2[3][1] = fma2(a23, B3, acc2[3][1]);
    }

    float* __restrict__ dst = &g_P2[blockIdx.y][0];
    #pragma unroll
    for (int q = 0; q < 4; q++) {
        float2 lo = unpack2(acc2[q][0]);   // rows +0, +1
        float2 hi = unpack2(acc2[q][1]);   // rows +2, +3
        int col = tx + 32 * q;
        dst[(m0 + ty * 4 + 0) * CC + col] = lo.x;
        dst[(m0 + ty * 4 + 1) * CC + col] = lo.y;
        dst[(m0 + ty * 4 + 2) * CC + col] = hi.x;
        dst[(m0 + ty * 4 + 3) * CC + col] = hi.y;
    }
}

// ---------------- K3: half-split loss + last-block final ----------------------
// grid (CC, 2), 128 threads. thread = (ksg 0..3, b4 0..31), 8 independent
// LDG.128 per thread. Loss is additive across CR/CT halves.
__global__ void __launch_bounds__(128) k_loss(float* __restrict__ out) {
    int a    = blockIdx.x;
    int half = blockIdx.y;          // 0 = CR(G1), 1 = CT(G2)
    int tid  = threadIdx.x;
    int ksg  = tid >> 5;            // 0..3  (8 slices each)
    int b4   = tid & 31;            // float4 group over b
    int m    = half * CC + a;

    const float4* __restrict__ base = (const float4*)(&g_P2[0][m * CC]);
    float4 p;
    {
        float4 t0 = base[(ksg * 8 + 0) * (MTOT * CC / 4) + b4];
        float4 t1 = base[(ksg * 8 + 1) * (MTOT * CC / 4) + b4];
        float4 t2 = base[(ksg * 8 + 2) * (MTOT * CC / 4) + b4];
        float4 t3 = base[(ksg * 8 + 3) * (MTOT * CC / 4) + b4];
        float4 t4 = base[(ksg * 8 + 4) * (MTOT * CC / 4) + b4];
        float4 t5 = base[(ksg * 8 + 5) * (MTOT * CC / 4) + b4];
        float4 t6 = base[(ksg * 8 + 6) * (MTOT * CC / 4) + b4];
        float4 t7 = base[(ksg * 8 + 7) * (MTOT * CC / 4) + b4];
        p.x = ((t0.x + t1.x) + (t2.x + t3.x)) + ((t4.x + t5.x) + (t6.x + t7.x));
        p.y = ((t0.y + t1.y) + (t2.y + t3.y)) + ((t4.y + t5.y) + (t6.y + t7.y));
        p.z = ((t0.z + t1.z) + (t2.z + t3.z)) + ((t4.z + t5.z) + (t6.z + t7.z));
        p.w = ((t0.w + t1.w) + (t2.w + t3.w)) + ((t4.w + t5.w) + (t6.w + t7.w));
    }

    __shared__ float4 sP[4][32];
    __shared__ float  sred[32];
    sP[ksg][b4] = p;
    __syncthreads();

    if (tid < 32) {
        int bg = tid;                    // b-group: b = bg*4..+3
        float4 p0 = sP[0][bg], p1 = sP[1][bg], p2 = sP[2][bg], p3 = sP[3][bg];
        float G[4] = { (p0.x + p1.x) + (p2.x + p3.x),
                       (p0.y + p1.y) + (p2.y + p3.y),
                       (p0.z + p1.z) + (p2.z + p3.z),
                       (p0.w + p1.w) + (p2.w + p3.w) };

        float nA = g_nPart[0][half][a] + g_nPart[1][half][a];
        float wa = (float)g_cnt[a];

        float acc = 0.f;
        #pragma unroll
        for (int j = 0; j < 4; j++) {
            int b = bg * 4 + j;
            float nMb = g_nPart[0][2][b] + g_nPart[1][2][b];
            float sq  = fmaxf(nA + nMb - 2.f * G[j], 1e-12f);
            float wgt = wa * (float)g_cnt[b];
            float term;
            if (a == b) {
                term = sq;              // label==1 half-term: clamped sq dist
            } else {
                term = 0.f;             // label==0: relu(0.5 - sq^(1/4))^2
                if (sq < 0.0625f) {
                    float dd = sqrtf(sqrtf(sq) + 1e-10f);
                    float r  = fmaxf(0.5f - dd, 0.f);
                    term = r * r;
                }
            }
            acc += wgt * term;
        }
        sred[bg] = acc;
    }
    __syncthreads();
    if (tid < 16) sred[tid] += sred[tid + 16];
    __syncthreads();
    if (tid < 8)  sred[tid] += sred[tid + 8];
    __syncthreads();
    if (tid < 4)  sred[tid] += sred[tid + 4];
    __syncthreads();
    if (tid < 2)  sred[tid] += sred[tid + 2];
    __syncthreads();
    if (tid == 0) g_la2[half * CC + a] = sred[0] + sred[1];

    // last-block final reduce over 256 partials (deterministic fixed order)
    __shared__ int s_last;
    if (tid == 0) {
        __threadfence();
        int t = atomicAdd(&g_ctr, 1);
        s_last = (t == 2 * CC - 1) ? 1 : 0;
    }
    __syncthreads();
    if (s_last) {
        __shared__ float fin[128];
        fin[tid] = g_la2[tid] + g_la2[CC + tid];
        __syncthreads();
        for (int s = 64; s > 0; s >>= 1) {
            if (tid < s) fin[tid] += fin[tid + s];
            __syncthreads();
        }
        if (tid == 0) {
            out[0] = fin[0] * (1.0f / ((float)NN * (float)NN));
            g_ctr = 0;   // reset for next graph replay
        }
    }
}

// ---------------- launch ----------------
extern "C" void kernel_launch(void* const* d_in, const int* in_sizes, int n_in,
                              void* d_out, int out_size) {
    const float* m1 = (const float*)d_in[0];
    const float* m2 = (const float*)d_in[1];
    const int*   tg = (const int*)d_in[2];
    float* out = (float*)d_out;

    k_means<<<dim3(CC, 2), 256>>>(m1, m2, tg);
    k_gram<<<dim3(MTOT / MT, KS), 256>>>();
    k_loss<<<dim3(CC, 2), 128>>>(out);
}

// round 11
// speedup vs baseline: 1.0753x; 1.0753x over previous
#include <cuda_runtime.h>

// Problem constants
#define NN   4096
#define DD   2048
#define CC   128
#define D4   (DD/4)          // 512 float4 per row
#define MTOT 256             // stacked rows: 0..127 = CR, 128..255 = CT
#define MT   32              // gram m-tile per block
#define KS   32              // k slices
#define KSL  64              // k per slice (KS*KSL == DD)

// ---------------- device scratch (no allocation allowed) ----------------
__device__ int   g_cnt[CC];
__device__ float g_C  [MTOT * DD];       // class means [m][k]: CR rows then CT rows
__device__ float g_nPart[4][3][CC];      // per-col-quarter norm partials (R,T,M)
__device__ float g_P2[KS][MTOT * CC];    // Gram K-partials, fixed slots (4 MB)
__device__ float g_la2[2 * CC];          // per (half, class-row) loss partials
__device__ int   g_ctr = 0;              // last-block counter (self-resetting)

// ---------------- f32x2 helpers (FFMA2 path) ----------------
__device__ __forceinline__ unsigned long long pack2(float x, float y) {
    unsigned long long r;
    asm("mov.b64 %0, {%1, %2};" : "=l"(r) : "f"(x), "f"(y));
    return r;
}
__device__ __forceinline__ unsigned long long fma2(unsigned long long a,
                                                   unsigned long long b,
                                                   unsigned long long c) {
    unsigned long long d;
    asm("fma.rn.f32x2 %0, %1, %2, %3;" : "=l"(d) : "l"(a), "l"(b), "l"(c));
    return d;
}
__device__ __forceinline__ float2 unpack2(unsigned long long v) {
    float2 f;
    asm("mov.b64 {%0, %1}, %2;" : "=f"(f.x), "=f"(f.y) : "l"(v));
    return f;
}
__device__ __forceinline__ void add4(float4& a, const float4 b) {
    a.x += b.x; a.y += b.y; a.z += b.z; a.w += b.w;
}

// ---------------- K1: fused warp-scan classlist + per-class means + norms -----
// grid (CC, 4), 128 threads. Warp-local scans, deterministic concat, then the
// column-quarter gather with 4 independent accumulator sets per modality so
// ptxas can front-batch 16 LDG.128 per unrolled iteration (MLP=16).
__global__ void __launch_bounds__(128) k_means(const float* __restrict__ m1,
                                               const float* __restrict__ m2,
                                               const int*   __restrict__ targets) {
    int c = blockIdx.x, y = blockIdx.y, tid = threadIdx.x;
    int lane = tid & 31, warp = tid >> 5;

    __shared__ int s_list[4][1024];   // per-warp candidate lists (worst-case safe)
    __shared__ int s_cnt[4];
    __shared__ int s_idx[NN];

    // warp w scans targets[w*1024 .. +1024) independently — no block barriers
    {
        int base = warp * 1024;
        int cntw = 0;
        unsigned lt = (1u << lane) - 1u;
        #pragma unroll 4
        for (int j = 0; j < 32; j++) {
            int i = base + j * 32 + lane;
            int t = targets[i];
            bool flag = (t == c);
            unsigned mask = __ballot_sync(0xffffffffu, flag);
            if (flag) s_list[warp][cntw + __popc(mask & lt)] = i;
            cntw += __popc(mask);
        }
        if (lane == 0) s_cnt[warp] = cntw;
    }
    __syncthreads();

    int cw0 = s_cnt[0], cw1 = s_cnt[1], cw2 = s_cnt[2], cw3 = s_cnt[3];
    int cnt = cw0 + cw1 + cw2 + cw3;
    if (cnt > NN) cnt = NN;
    {   // deterministic concat: warp w copies its list to its fixed offset
        int off = (warp > 0 ? cw0 : 0) + (warp > 1 ? cw1 : 0) + (warp > 2 ? cw2 : 0);
        int n = s_cnt[warp];
        for (int i = lane; i < n; i += 32) s_idx[off + i] = s_list[warp][i];
    }
    __syncthreads();

    // gather: this block owns 128 consecutive float4 columns
    int col4 = y * 128 + tid;     // 0..511
    const float4* __restrict__ m1v = (const float4*)m1;
    const float4* __restrict__ m2v = (const float4*)m2;

    // 4 independent accumulator sets per modality — no single dep chain
    float4 aR0 = make_float4(0.f,0.f,0.f,0.f), aR1 = aR0, aR2 = aR0, aR3 = aR0;
    float4 aT0 = aR0, aT1 = aR0, aT2 = aR0, aT3 = aR0;

    int k = 0;
    for (; k + 8 <= cnt; k += 8) {
        int r0 = s_idx[k+0], r1 = s_idx[k+1], r2 = s_idx[k+2], r3 = s_idx[k+3];
        int r4 = s_idx[k+4], r5 = s_idx[k+5], r6 = s_idx[k+6], r7 = s_idx[k+7];
        // 16 independent loads (distinct destinations) — batched by ptxas
        float4 x0 = m1v[r0 * D4 + col4];
        float4 x1 = m1v[r1 * D4 + col4];
        float4 x2 = m1v[r2 * D4 + col4];
        float4 x3 = m1v[r3 * D4 + col4];
        float4 x4 = m1v[r4 * D4 + col4];
        float4 x5 = m1v[r5 * D4 + col4];
        float4 x6 = m1v[r6 * D4 + col4];
        float4 x7 = m1v[r7 * D4 + col4];
        float4 z0 = m2v[r0 * D4 + col4];
        float4 z1 = m2v[r1 * D4 + col4];
        float4 z2 = m2v[r2 * D4 + col4];
        float4 z3 = m2v[r3 * D4 + col4];
        float4 z4 = m2v[r4 * D4 + col4];
        float4 z5 = m2v[r5 * D4 + col4];
        float4 z6 = m2v[r6 * D4 + col4];
        float4 z7 = m2v[r7 * D4 + col4];
        add4(aR0, x0); add4(aR1, x1); add4(aR2, x2); add4(aR3, x3);
        add4(aR0, x4); add4(aR1, x5); add4(aR2, x6); add4(aR3, x7);
        add4(aT0, z0); add4(aT1, z1); add4(aT2, z2); add4(aT3, z3);
        add4(aT0, z4); add4(aT1, z5); add4(aT2, z6); add4(aT3, z7);
    }
    for (; k < cnt; k++) {
        int r = s_idx[k];
        float4 a = m1v[r * D4 + col4];
        float4 b = m2v[r * D4 + col4];
        add4(aR0, a);
        add4(aT0, b);
    }

    // fixed-order combine of the 4 sets
    float4 sR = make_float4(((aR0.x + aR1.x) + (aR2.x + aR3.x)),
                            ((aR0.y + aR1.y) + (aR2.y + aR3.y)),
                            ((aR0.z + aR1.z) + (aR2.z + aR3.z)),
                            ((aR0.w + aR1.w) + (aR2.w + aR3.w)));
    float4 sT = make_float4(((aT0.x + aT1.x) + (aT2.x + aT3.x)),
                            ((aT0.y + aT1.y) + (aT2.y + aT3.y)),
                            ((aT0.z + aT1.z) + (aT2.z + aT3.z)),
                            ((aT0.w + aT1.w) + (aT2.w + aT3.w)));

    float inv = 1.0f / (float)(cnt > 0 ? cnt : 1);
    float4 mr = make_float4(sR.x * inv, sR.y * inv, sR.z * inv, sR.w * inv);
    float4 mt = make_float4(sT.x * inv, sT.y * inv, sT.z * inv, sT.w * inv);
    float4 mm = make_float4(0.5f * (mr.x + mt.x), 0.5f * (mr.y + mt.y),
                            0.5f * (mr.z + mt.z), 0.5f * (mr.w + mt.w));

    ((float4*)g_C)[c * D4 + col4]        = mr;
    ((float4*)g_C)[(CC + c) * D4 + col4] = mt;

    // norm partials over this column quarter (fixed-tree reduce)
    float pR = mr.x * mr.x + mr.y * mr.y + mr.z * mr.z + mr.w * mr.w;
    float pT = mt.x * mt.x + mt.y * mt.y + mt.z * mt.z + mt.w * mt.w;
    float pM = mm.x * mm.x + mm.y * mm.y + mm.z * mm.z + mm.w * mm.w;
    __shared__ float r0s[128], r1s[128], r2s[128];
    r0s[tid] = pR; r1s[tid] = pT; r2s[tid] = pM;
    __syncthreads();
    for (int s = 64; s > 0; s >>= 1) {
        if (tid < s) { r0s[tid] += r0s[tid + s]; r1s[tid] += r1s[tid + s]; r2s[tid] += r2s[tid + s]; }
        __syncthreads();
    }
    if (tid == 0) {
        g_nPart[y][0][c] = r0s[0];
        g_nPart[y][1][c] = r1s[0];
        g_nPart[y][2][c] = r2s[0];
        if (y == 0) g_cnt[c] = cnt;
    }
}

// ---------------- K2: Gram with inline transpose + B build --------------------
// grid (MTOT/MT = 8, KS = 32) = 256 blocks, 256 threads.
__global__ void __launch_bounds__(256) k_gram() {
    __shared__ float Acm[MT][67];       // [row][k], 8.6 KB
    __shared__ float Bcm[CC][67];       // [c][k] = Cm, 34.3 KB

    int tid = threadIdx.x;
    int m0  = blockIdx.x * MT;
    int kb4 = blockIdx.y * (KSL / 4);

    const float4* __restrict__ c4 = (const float4*)g_C;

    // A fill: 32 rows x 16 float4 = 512 float4 (2 per thread), coalesced LDG
    #pragma unroll
    for (int i = 0; i < 2; i++) {
        int idx = tid + i * 256;           // 0..511
        int r = idx >> 4, j4 = idx & 15;
        float4 v = c4[(m0 + r) * D4 + kb4 + j4];
        Acm[r][j4 * 4 + 0] = v.x;
        Acm[r][j4 * 4 + 1] = v.y;
        Acm[r][j4 * 4 + 2] = v.z;
        Acm[r][j4 * 4 + 3] = v.w;
    }
    // B fill: 128 classes x 16 float4, CR + CT pair per float4 (8 per thread)
    #pragma unroll
    for (int i = 0; i < 8; i++) {
        int idx = tid + i * 256;           // 0..2047
        int cc = idx >> 4, j4 = idx & 15;
        float4 vR = c4[cc * D4 + kb4 + j4];
        float4 vT = c4[(CC + cc) * D4 + kb4 + j4];
        Bcm[cc][j4 * 4 + 0] = 0.5f * (vR.x + vT.x);
        Bcm[cc][j4 * 4 + 1] = 0.5f * (vR.y + vT.y);
        Bcm[cc][j4 * 4 + 2] = 0.5f * (vR.z + vT.z);
        Bcm[cc][j4 * 4 + 3] = 0.5f * (vR.w + vT.w);
    }
    __syncthreads();

    int tx = tid & 31;     // cols tx, tx+32, tx+64, tx+96
    int ty = tid >> 5;     // rows ty*4 .. ty*4+3 (warp-uniform -> LDS broadcast)

    // acc2[q][p]: col q, p=0 rows (0,1), p=1 rows (2,3)
    unsigned long long acc2[4][2];
    #pragma unroll
    for (int q = 0; q < 4; q++) { acc2[q][0] = 0ull; acc2[q][1] = 0ull; }

    #pragma unroll 8
    for (int k = 0; k < KSL; k++) {
        float a0 = Acm[ty * 4 + 0][k];
        float a1 = Acm[ty * 4 + 1][k];
        float a2 = Acm[ty * 4 + 2][k];
        float a3 = Acm[ty * 4 + 3][k];
        float b0 = Bcm[tx      ][k];
        float b1 = Bcm[tx + 32 ][k];
        float b2 = Bcm[tx + 64 ][k];
        float b3 = Bcm[tx + 96 ][k];
        unsigned long long a01 = pack2(a0, a1);
        unsigned long long a23 = pack2(a2, a3);
        unsigned long long B0 = pack2(b0, b0);
        unsigned long long B1 = pack2(b1, b1);
        unsigned long long B2 = pack2(b2, b2);
        unsigned long long B3 = pack2(b3, b3);
        acc2[0][0] = fma2(a01, B0, acc2[0][0]);
        acc2[0][1] = fma2(a23, B0, acc2[0][1]);
        acc2[1][0] = fma2(a01, B1, acc2[1][0]);
        acc2[1][1] = fma2(a23, B1, acc2[1][1]);
        acc2[2][0] = fma2(a01, B2, acc2[2][0]);
        acc2[2][1] = fma2(a23, B2, acc2[2][1]);
        acc2[3][0] = fma2(a01, B3, acc2[3][0]);
        acc2[3][1] = fma2(a23, B3, acc2[3][1]);
    }

    float* __restrict__ dst = &g_P2[blockIdx.y][0];
    #pragma unroll
    for (int q = 0; q < 4; q++) {
        float2 lo = unpack2(acc2[q][0]);   // rows +0, +1
        float2 hi = unpack2(acc2[q][1]);   // rows +2, +3
        int col = tx + 32 * q;
        dst[(m0 + ty * 4 + 0) * CC + col] = lo.x;
        dst[(m0 + ty * 4 + 1) * CC + col] = lo.y;
        dst[(m0 + ty * 4 + 2) * CC + col] = hi.x;
        dst[(m0 + ty * 4 + 3) * CC + col] = hi.y;
    }
}

// ---------------- K3: half-split loss + last-block final ----------------------
// grid (CC, 2), 128 threads. thread = (ksg 0..3, b4 0..31), 8 independent
// LDG.128 per thread. Loss is additive across CR/CT halves.
__global__ void __launch_bounds__(128) k_loss(float* __restrict__ out) {
    int a    = blockIdx.x;
    int half = blockIdx.y;          // 0 = CR(G1), 1 = CT(G2)
    int tid  = threadIdx.x;
    int ksg  = tid >> 5;            // 0..3  (8 slices each)
    int b4   = tid & 31;            // float4 group over b
    int m    = half * CC + a;

    const float4* __restrict__ base = (const float4*)(&g_P2[0][m * CC]);
    float4 p;
    {
        float4 t0 = base[(ksg * 8 + 0) * (MTOT * CC / 4) + b4];
        float4 t1 = base[(ksg * 8 + 1) * (MTOT * CC / 4) + b4];
        float4 t2 = base[(ksg * 8 + 2) * (MTOT * CC / 4) + b4];
        float4 t3 = base[(ksg * 8 + 3) * (MTOT * CC / 4) + b4];
        float4 t4 = base[(ksg * 8 + 4) * (MTOT * CC / 4) + b4];
        float4 t5 = base[(ksg * 8 + 5) * (MTOT * CC / 4) + b4];
        float4 t6 = base[(ksg * 8 + 6) * (MTOT * CC / 4) + b4];
        float4 t7 = base[(ksg * 8 + 7) * (MTOT * CC / 4) + b4];
        p.x = ((t0.x + t1.x) + (t2.x + t3.x)) + ((t4.x + t5.x) + (t6.x + t7.x));
        p.y = ((t0.y + t1.y) + (t2.y + t3.y)) + ((t4.y + t5.y) + (t6.y + t7.y));
        p.z = ((t0.z + t1.z) + (t2.z + t3.z)) + ((t4.z + t5.z) + (t6.z + t7.z));
        p.w = ((t0.w + t1.w) + (t2.w + t3.w)) + ((t4.w + t5.w) + (t6.w + t7.w));
    }

    __shared__ float4 sP[4][32];
    __shared__ float  sred[32];
    sP[ksg][b4] = p;
    __syncthreads();

    if (tid < 32) {
        int bg = tid;                    // b-group: b = bg*4..+3
        float4 p0 = sP[0][bg], p1 = sP[1][bg], p2 = sP[2][bg], p3 = sP[3][bg];
        float G[4] = { (p0.x + p1.x) + (p2.x + p3.x),
                       (p0.y + p1.y) + (p2.y + p3.y),
                       (p0.z + p1.z) + (p2.z + p3.z),
                       (p0.w + p1.w) + (p2.w + p3.w) };

        float nA = ((g_nPart[0][half][a] + g_nPart[1][half][a])
                  + (g_nPart[2][half][a] + g_nPart[3][half][a]));
        float wa = (float)g_cnt[a];

        float acc = 0.f;
        #pragma unroll
        for (int j = 0; j < 4; j++) {
            int b = bg * 4 + j;
            float nMb = ((g_nPart[0][2][b] + g_nPart[1][2][b])
                       + (g_nPart[2][2][b] + g_nPart[3][2][b]));
            float sq  = fmaxf(nA + nMb - 2.f * G[j], 1e-12f);
            float wgt = wa * (float)g_cnt[b];
            float term;
            if (a == b) {
                term = sq;              // label==1 half-term: clamped sq dist
            } else {
                term = 0.f;             // label==0: relu(0.5 - sq^(1/4))^2
                if (sq < 0.0625f) {
                    float dd = sqrtf(sqrtf(sq) + 1e-10f);
                    float r  = fmaxf(0.5f - dd, 0.f);
                    term = r * r;
                }
            }
            acc += wgt * term;
        }
        sred[bg] = acc;
    }
    __syncthreads();
    if (tid < 16) sred[tid] += sred[tid + 16];
    __syncthreads();
    if (tid < 8)  sred[tid] += sred[tid + 8];
    __syncthreads();
    if (tid < 4)  sred[tid] += sred[tid + 4];
    __syncthreads();
    if (tid < 2)  sred[tid] += sred[tid + 2];
    __syncthreads();
    if (tid == 0) g_la2[half * CC + a] = sred[0] + sred[1];

    // last-block final reduce over 256 partials (deterministic fixed order)
    __shared__ int s_last;
    if (tid == 0) {
        __threadfence();
        int t = atomicAdd(&g_ctr, 1);
        s_last = (t == 2 * CC - 1) ? 1 : 0;
    }
    __syncthreads();
    if (s_last) {
        __shared__ float fin[128];
        fin[tid] = g_la2[tid] + g_la2[CC + tid];
        __syncthreads();
        for (int s = 64; s > 0; s >>= 1) {
            if (tid < s) fin[tid] += fin[tid + s];
            __syncthreads();
        }
        if (tid == 0) {
            out[0] = fin[0] * (1.0f / ((float)NN * (float)NN));
            g_ctr = 0;   // reset for next graph replay
        }
    }
}

// ---------------- launch ----------------
extern "C" void kernel_launch(void* const* d_in, const int* in_sizes, int n_in,
                              void* d_out, int out_size) {
    const float* m1 = (const float*)d_in[0];
    const float* m2 = (const float*)d_in[1];
    const int*   tg = (const int*)d_in[2];
    float* out = (float*)d_out;

    k_means<<<dim3(CC, 4), 128>>>(m1, m2, tg);
    k_gram<<<dim3(MTOT / MT, KS), 256>>>();
    k_loss<<<dim3(CC, 2), 128>>>(out);
}